// round 6
// baseline (speedup 1.0000x reference)
#include <cuda_runtime.h>
#include <cstdint>

// MessagePassing: out[row[e]] += x[col[e]]  for e in [0, E)
// x: [N, 32] f32; edge_index: [2, E] int32. row = ei[0:E], col = ei[E:2E].
//
// Model: 8 x 32B sectors/edge (128B gather + 128B RED) through L1tex at
// ~1 sector/cyc/SM is the structural floor (~43us chip-wide); R4 hit 79.6%
// L1 util. This version: U=4 edges per 8-lane group, fixed-grid grid-stride
// loop with explicit prefetch of the next iteration's indices, to keep the
// LSU fed across iterations and push L1tex util higher. CSR rebuild was
// costed and rejected: build sector cost ~= aggregate sector savings.

#define D 32
#define U 4

__global__ void mp_zero_kernel(float4* __restrict__ out, int n4) {
    int i = blockIdx.x * blockDim.x + threadIdx.x;
    if (i < n4) out[i] = make_float4(0.f, 0.f, 0.f, 0.f);
}

__device__ __forceinline__ void red_add_v4(float* dst, float4 v) {
    asm volatile("red.global.add.v4.f32 [%0], {%1, %2, %3, %4};"
                 :: "l"(dst), "f"(v.x), "f"(v.y), "f"(v.z), "f"(v.w)
                 : "memory");
}

// Assumes E % U == 0 (fast path); tail handled by a tiny scalar kernel.
__global__ __launch_bounds__(256, 6) void mp_scatter_kernel(
        const float* __restrict__ x,
        const int* __restrict__ ei,
        float* __restrict__ out,
        int E, int N, int ngroups) {
    const int chunk = (threadIdx.x & 7) << 2;   // float offset in 32-float row
    const int g0 = (blockIdx.x * blockDim.x + threadIdx.x) >> 3;
    const int gstride = (gridDim.x * blockDim.x) >> 3;

    if (g0 >= ngroups) return;

    // prefetch first iteration's indices
    int4 rows = *reinterpret_cast<const int4*>(ei + g0 * U);
    int4 cols = *reinterpret_cast<const int4*>(ei + E + g0 * U);

    for (int g = g0; g < ngroups; g += gstride) {
        int r[U] = {rows.x, rows.y, rows.z, rows.w};
        int c[U] = {cols.x, cols.y, cols.z, cols.w};

        // issue the 4 independent gathers immediately
        float4 v[U];
        #pragma unroll
        for (int i = 0; i < U; i++) {
            int cc = ((unsigned)c[i] < (unsigned)N) ? c[i] : 0;
            v[i] = __ldg(reinterpret_cast<const float4*>(
                       x + (long long)cc * D + chunk));
        }

        // prefetch next iteration's indices while gathers are in flight
        int gn = g + gstride;
        if (gn < ngroups) {
            rows = *reinterpret_cast<const int4*>(ei + gn * U);
            cols = *reinterpret_cast<const int4*>(ei + E + gn * U);
        }

        // fire-and-forget vectorized reductions
        #pragma unroll
        for (int i = 0; i < U; i++) {
            if ((unsigned)r[i] < (unsigned)N && (unsigned)c[i] < (unsigned)N)
                red_add_v4(out + (long long)r[i] * D + chunk, v[i]);
        }
    }
}

// Scalar tail for E % U != 0 (not hit for E = 1.6M, but kept for safety).
__global__ void mp_tail_kernel(const float* __restrict__ x,
                               const int* __restrict__ ei,
                               float* __restrict__ out,
                               int Estart, int E, int N) {
    int t = blockIdx.x * blockDim.x + threadIdx.x;
    int e = Estart + (t >> 3);
    if (e >= E) return;
    int chunk = (t & 7) << 2;
    int r = ei[e];
    int c = ei[E + e];
    if ((unsigned)r >= (unsigned)N || (unsigned)c >= (unsigned)N) return;
    float4 v = __ldg(reinterpret_cast<const float4*>(
                   x + (long long)c * D + chunk));
    red_add_v4(out + (long long)r * D + chunk, v);
}

extern "C" void kernel_launch(void* const* d_in, const int* in_sizes, int n_in,
                              void* d_out, int out_size) {
    const float* x = (const float*)d_in[0];
    const int* ei = (const int*)d_in[1];
    float* out = (float*)d_out;

    const int E = in_sizes[1] / 2;    // edge_index has 2*E elements
    const int N = in_sizes[0] / D;    // number of nodes
    const int n4 = out_size / 4;      // out: N*32 floats -> N*8 float4

    // 1) zero the output (harness poisons it with 0xAA)
    {
        int threads = 256;
        int blocks = (n4 + threads - 1) / threads;
        mp_zero_kernel<<<blocks, threads>>>((float4*)out, n4);
    }

    // 2) gather + vectorized scatter-add: grid-stride, U edges per group-iter
    {
        int ngroups = E / U;               // full groups
        int threads = 256;
        // fixed grid: ~8 blocks/SM * 148 SMs, but never more than work
        long long lanes = (long long)ngroups * 8;
        int maxblocks = (int)((lanes + threads - 1) / threads);
        int blocks = 1184 < maxblocks ? 1184 : maxblocks;
        mp_scatter_kernel<<<blocks, threads>>>(x, ei, out, E, N, ngroups);

        int tail = E - ngroups * U;
        if (tail > 0) {
            int tl = tail * 8;
            mp_tail_kernel<<<(tl + 255) / 256, 256>>>(x, ei, out,
                                                      ngroups * U, E, N);
        }
    }
}

// round 7
// speedup vs baseline: 1.0921x; 1.0921x over previous
#include <cuda_runtime.h>
#include <cstdint>

// MessagePassing: out[row[e]] += x[col[e]]  for e in [0, E)
// x: [N, 32] f32; edge_index: [2, E] int32. row = ei[0:E], col = ei[E:2E].
//
// Model (R6 post-mortem): R4's scatter moves ~423MB through LTS in 38.9us
// = ~5860 B/cyc = ~93% of the measured ~6300 B/cyc B300 LTS cap. The kernel
// is L2-fabric throughput-bound; extra MLP (R5/R6) only lost occupancy.
// This round: restore R4's proven config exactly (U=4, one-shot grid,
// 8 lanes/edge, LDG.128 gather + red.global.add.v4.f32) and replace the
// zero kernel with cudaMemsetAsync to cut fixed overhead.

#define D 32
#define U 4

__device__ __forceinline__ void red_add_v4(float* dst, float4 v) {
    asm volatile("red.global.add.v4.f32 [%0], {%1, %2, %3, %4};"
                 :: "l"(dst), "f"(v.x), "f"(v.y), "f"(v.z), "f"(v.w)
                 : "memory");
}

__global__ void mp_scatter_kernel(const float* __restrict__ x,
                                  const int* __restrict__ ei,
                                  float* __restrict__ out,
                                  int E, int N) {
    int t = blockIdx.x * blockDim.x + threadIdx.x;
    int chunk = (t & 7) << 2;      // float offset within the 32-float row
    int g = t >> 3;                // edge-group id: edges [g*U, g*U+U)
    int e0 = g * U;
    if (e0 >= E) return;

    if (e0 + U <= E && (E & 3) == 0) {
        // fast path: vector index loads (16B-aligned since E % 4 == 0)
        int4 rows = *reinterpret_cast<const int4*>(ei + e0);
        int4 cols = *reinterpret_cast<const int4*>(ei + E + e0);

        int r[U] = {rows.x, rows.y, rows.z, rows.w};
        int c[U] = {cols.x, cols.y, cols.z, cols.w};

        float4 v[U];
        #pragma unroll
        for (int i = 0; i < U; i++) {
            int cc = ((unsigned)c[i] < (unsigned)N) ? c[i] : 0;
            v[i] = __ldg(reinterpret_cast<const float4*>(
                       x + (long long)cc * D + chunk));
        }
        #pragma unroll
        for (int i = 0; i < U; i++) {
            if ((unsigned)r[i] < (unsigned)N && (unsigned)c[i] < (unsigned)N)
                red_add_v4(out + (long long)r[i] * D + chunk, v[i]);
        }
    } else {
        // tail path: scalar index loads
        #pragma unroll
        for (int i = 0; i < U; i++) {
            int e = e0 + i;
            if (e >= E) break;
            int r = ei[e];
            int c = ei[E + e];
            if ((unsigned)r >= (unsigned)N || (unsigned)c >= (unsigned)N)
                continue;
            float4 v = __ldg(reinterpret_cast<const float4*>(
                           x + (long long)c * D + chunk));
            red_add_v4(out + (long long)r * D + chunk, v);
        }
    }
}

extern "C" void kernel_launch(void* const* d_in, const int* in_sizes, int n_in,
                              void* d_out, int out_size) {
    const float* x = (const float*)d_in[0];
    const int* ei = (const int*)d_in[1];
    float* out = (float*)d_out;

    const int E = in_sizes[1] / 2;    // edge_index has 2*E elements
    const int N = in_sizes[0] / D;    // number of nodes

    // 1) zero the output (harness poisons it with 0xAA); async memset is
    //    graph-capturable and cheaper than a launch.
    cudaMemsetAsync(out, 0, (size_t)out_size * sizeof(float), 0);

    // 2) gather + vectorized scatter-add, U edges per thread (R4 config)
    {
        long long groups = ((long long)E + U - 1) / U;
        long long total = groups * 8;
        int threads = 256;
        int blocks = (int)((total + threads - 1) / threads);
        mp_scatter_kernel<<<blocks, threads>>>(x, ei, out, E, N);
    }
}

// round 8
// speedup vs baseline: 1.0988x; 1.0062x over previous
#include <cuda_runtime.h>
#include <cstdint>

// MessagePassing: out[row[e]] += x[col[e]]  for e in [0, E)
// x: [N, 32] f32; edge_index: [2, E] int32. row = ei[0:E], col = ei[E:2E].
//
// Converged design (R1-R7): edge-parallel, 8 lanes per edge x 16B chunks,
// LDG.128 gather + red.global.add.v4.f32 scatter. Measured at ~93% of the
// ~6300 B/cyc LTS chip cap (~423MB LTS traffic in ~39us). Alternatives
// costed and rejected: CSR rebuild (build sectors ~= savings), SMEM-binned
// accumulation (ATOMS ~2 B/cyc/SM, 10x worse than the 192 LTS atomic ALUs).
// This round: hot path stripped of bounds checks and runtime branches;
// tail split at launch; NC index loads.

#define D 32
#define U 4

__device__ __forceinline__ void red_add_v4(float* dst, float4 v) {
    asm volatile("red.global.add.v4.f32 [%0], {%1, %2, %3, %4};"
                 :: "l"(dst), "f"(v.x), "f"(v.y), "f"(v.z), "f"(v.w)
                 : "memory");
}

// Handles full groups only: edges [0, ngroups*U). No branches in hot path.
__global__ __launch_bounds__(256) void mp_scatter_kernel(
        const float* __restrict__ x,
        const int* __restrict__ ei,
        float* __restrict__ out,
        int E, int ngroups) {
    int t = blockIdx.x * blockDim.x + threadIdx.x;
    int g = t >> 3;                 // edge-group id: edges [g*U, g*U+U)
    if (g >= ngroups) return;
    int chunk = (t & 7) << 2;       // float offset within the 32-float row
    int e0 = g * U;

    int4 rows = __ldg(reinterpret_cast<const int4*>(ei + e0));
    int4 cols = __ldg(reinterpret_cast<const int4*>(ei + E + e0));

    int r[U] = {rows.x, rows.y, rows.z, rows.w};
    int c[U] = {cols.x, cols.y, cols.z, cols.w};

    float4 v[U];
    #pragma unroll
    for (int i = 0; i < U; i++)
        v[i] = __ldg(reinterpret_cast<const float4*>(
                   x + (long long)c[i] * D + chunk));

    #pragma unroll
    for (int i = 0; i < U; i++)
        red_add_v4(out + (long long)r[i] * D + chunk, v[i]);
}

// Scalar tail for E % U != 0 (not hit for E = 1.6M; kept for generality).
__global__ void mp_tail_kernel(const float* __restrict__ x,
                               const int* __restrict__ ei,
                               float* __restrict__ out,
                               int Estart, int E) {
    int t = blockIdx.x * blockDim.x + threadIdx.x;
    int e = Estart + (t >> 3);
    if (e >= E) return;
    int chunk = (t & 7) << 2;
    int r = ei[e];
    int c = ei[E + e];
    float4 v = __ldg(reinterpret_cast<const float4*>(
                   x + (long long)c * D + chunk));
    red_add_v4(out + (long long)r * D + chunk, v);
}

extern "C" void kernel_launch(void* const* d_in, const int* in_sizes, int n_in,
                              void* d_out, int out_size) {
    const float* x = (const float*)d_in[0];
    const int* ei = (const int*)d_in[1];
    float* out = (float*)d_out;

    const int E = in_sizes[1] / 2;    // edge_index has 2*E elements

    // 1) zero the output (harness poisons it with 0xAA)
    cudaMemsetAsync(out, 0, (size_t)out_size * sizeof(float), 0);

    // 2) gather + vectorized scatter-add, U edges per 8-lane group
    {
        int ngroups = E / U;
        long long total = (long long)ngroups * 8;
        int threads = 256;
        int blocks = (int)((total + threads - 1) / threads);
        mp_scatter_kernel<<<blocks, threads>>>(x, ei, out, E, ngroups);

        int tail = E - ngroups * U;
        if (tail > 0)
            mp_tail_kernel<<<(tail * 8 + 255) / 256, 256>>>(x, ei, out,
                                                            ngroups * U, E);
    }
}